// round 7
// baseline (speedup 1.0000x reference)
#include <cuda_runtime.h>
#include <cuda_bf16.h>
#include <math.h>
#include <stdint.h>

#define N_NODES   50000
#define IN_FEAT   128
#define HIDDEN    256
#define N_CLASSES 40
#define MAX_E     320000
#define BN_EPS    1e-5f

// ---------------- scratch (device globals; no allocation) ----------------
__device__ float g_bufA[N_NODES * HIDDEN];
__device__ float g_bufB[N_NODES * HIDDEN];
__device__ float g_bufC[N_NODES * HIDDEN];
__device__ float g_dinv[N_NODES];
__device__ int   g_cnt[N_NODES];
__device__ int   g_rowstart[N_NODES];
__device__ int   g_cursor[N_NODES];
__device__ int   g_total;
__device__ int   g_esrc[MAX_E];
__device__ float g_enrm[MAX_E];
__device__ float g_sum[HIDDEN];
__device__ float g_sumsq[HIDDEN];
__device__ float g_scale[HIDDEN];
__device__ float g_shift[HIDDEN];
__device__ int   g_is64;

// ---------------- dtype probe + zero scratch (grid-wide) ----------------
__global__ void k_detect_zero(const int* __restrict__ ei32, int n) {
    int i = blockIdx.x * blockDim.x + threadIdx.x;
    if (i < n) g_cnt[i] = 0;
    if (i < HIDDEN) { g_sum[i] = 0.0f; g_sumsq[i] = 0.0f; }
    if (i == 0) g_total = 0;
    if (blockIdx.x == 0) {
        __shared__ int nz;
        if (threadIdx.x == 0) nz = 0;
        __syncthreads();
        for (int j = threadIdx.x; j < 1024; j += blockDim.x)
            if (ei32[2 * j + 1] != 0) nz = 1;
        __syncthreads();
        if (threadIdx.x == 0) g_is64 = (nz == 0) ? 1 : 0;
    }
}
__device__ __forceinline__ int eget(const void* ei, long pos) {
    if (g_is64) return (int)__ldg(((const long long*)ei) + pos);
    return __ldg(((const int*)ei) + pos);
}

// ---------------- CSR build (unordered segments) ----------------
__global__ void k_hist(const void* __restrict__ ei, int E) {
    int e = blockIdx.x * blockDim.x + threadIdx.x;
    if (e >= E) return;
    atomicAdd(&g_cnt[eget(ei, (long)E + e)], 1);
}
__global__ void k_reserve(int n) {
    int i = blockIdx.x * blockDim.x + threadIdx.x;
    if (i >= n) return;
    int c = g_cnt[i];
    g_dinv[i] = rsqrtf(1.0f + (float)c);
    int pos = atomicAdd(&g_total, c);
    g_rowstart[i] = pos;
    g_cursor[i] = pos;
}
__global__ void k_fill(const void* __restrict__ ei, int E) {
    int e = blockIdx.x * blockDim.x + threadIdx.x;
    if (e >= E) return;
    int s = eget(ei, e);
    int d = eget(ei, (long)E + e);
    int pos = atomicAdd(&g_cursor[d], 1);
    g_esrc[pos] = s;
    g_enrm[pos] = g_dinv[s] * g_dinv[d];
}

// ---------------- HMMA helpers ----------------
__device__ __forceinline__ void ldm_x4(uint32_t* r, const void* p) {
    uint32_t a = (uint32_t)__cvta_generic_to_shared(p);
    asm volatile("ldmatrix.sync.aligned.m8n8.x4.shared.b16 {%0,%1,%2,%3}, [%4];"
                 : "=r"(r[0]), "=r"(r[1]), "=r"(r[2]), "=r"(r[3]) : "r"(a));
}
__device__ __forceinline__ void ldm_x4_t(uint32_t* r, const void* p) {
    uint32_t a = (uint32_t)__cvta_generic_to_shared(p);
    asm volatile("ldmatrix.sync.aligned.m8n8.x4.trans.shared.b16 {%0,%1,%2,%3}, [%4];"
                 : "=r"(r[0]), "=r"(r[1]), "=r"(r[2]), "=r"(r[3]) : "r"(a));
}
__device__ __forceinline__ void mma_bf16(float* c, const uint32_t* a, const uint32_t* b) {
    asm volatile(
        "mma.sync.aligned.m16n8k16.row.col.f32.bf16.bf16.f32 "
        "{%0,%1,%2,%3}, {%4,%5,%6,%7}, {%8,%9}, {%0,%1,%2,%3};"
        : "+f"(c[0]), "+f"(c[1]), "+f"(c[2]), "+f"(c[3])
        : "r"(a[0]), "r"(a[1]), "r"(a[2]), "r"(a[3]), "r"(b[0]), "r"(b[1]));
}
__device__ __forceinline__ void split_bf16(float v, unsigned short& h, unsigned short& l) {
    __nv_bfloat16 hb = __float2bfloat16(v);
    __nv_bfloat16 lb = __float2bfloat16(v - __bfloat162float(hb));
    h = __bfloat16_as_ushort(hb);
    l = __bfloat16_as_ushort(lb);
}

// ---------------- HMMA GEMM (register-prefetch pipelined) ----------------
// xw = act(A) @ W (+ bias); act = relu(a*scale+shift) if useScale
// DO_STATS: accumulate column sum/sumsq of the stored output into g_sum/g_sumsq.
template <int BN_T, bool DO_STATS>
__global__ void __launch_bounds__(256) gemm_mma(
    const float* __restrict__ A, const float* __restrict__ W,
    const float* __restrict__ scale, const float* __restrict__ shift,
    const float* __restrict__ bias,
    float* __restrict__ xw,
    int M, int K, int Nr)
{
    constexpr int BM = 128, BK = 32;
    constexpr int ASTR = BK + 8;
    constexpr int BSTR = BN_T + 8;
    constexpr int BN_W = BN_T / 2;
    constexpr int NT = BN_W / 8;
    constexpr int NG = BN_W / 16;
    constexpr int BP = BN_T / 32;

    __shared__ __nv_bfloat16 As[2][BM][ASTR];
    __shared__ __nv_bfloat16 Bs[2][BK][BSTR];
    __shared__ float sSc[HIDDEN], sSh[HIDDEN];

    const int tid = threadIdx.x;
    const int wid = tid >> 5, lane = tid & 31;
    const int warp_m = wid >> 1, warp_n = wid & 1;
    const int blockRow = blockIdx.x * BM;
    const int colBase = blockIdx.y * BN_T;
    const bool useScale = (scale != nullptr);

    if (useScale) {
        for (int i = tid; i < K; i += 256) { sSc[i] = scale[i]; sSh[i] = shift[i]; }
    }

    // A loader coords
    const int a_c4 = (tid & 7) * 4;
    const int a_row0 = tid >> 3;
    // B loader coords
    const int b_row = tid >> 3;
    const int b_c4 = (tid & 7) * 4;

    float4 pa[4], pb[BP];

    auto ldgA = [&](int k0) {
#pragma unroll
        for (int p = 0; p < 4; p++) {
            long gr = blockRow + a_row0 + p * 32;
            if (gr < M) pa[p] = *(const float4*)&A[gr * K + k0 + a_c4];
            else pa[p] = make_float4(0.f, 0.f, 0.f, 0.f);
        }
    };
    auto ldgB = [&](int k0) {
#pragma unroll
        for (int p = 0; p < BP; p++) {
            int gcol = colBase + b_c4 + p * 32;
            if (gcol < Nr) pb[p] = *(const float4*)&W[(long)(k0 + b_row) * Nr + gcol];
            else pb[p] = make_float4(0.f, 0.f, 0.f, 0.f);
        }
    };

    float acc[2][NT][4];
#pragma unroll
    for (int m = 0; m < 2; m++)
#pragma unroll
        for (int n = 0; n < NT; n++)
#pragma unroll
            for (int j = 0; j < 4; j++) acc[m][n][j] = 0.0f;

    const int nc = K / BK;
    ldgA(0); ldgB(0);
    if (useScale) __syncthreads();  // sSc/sSh ready

    for (int c = 0; c < nc; c++) {
        const int k0 = c * BK;
        // ---- convert + STS chunk c ----
#pragma unroll
        for (int p = 0; p < 4; p++) {
            float v[4] = {pa[p].x, pa[p].y, pa[p].z, pa[p].w};
            if (useScale) {
#pragma unroll
                for (int j = 0; j < 4; j++)
                    v[j] = fmaxf(0.0f, fmaf(v[j], sSc[k0 + a_c4 + j], sSh[k0 + a_c4 + j]));
            }
            unsigned short h[4], l[4];
#pragma unroll
            for (int j = 0; j < 4; j++) split_bf16(v[j], h[j], l[j]);
            int row = a_row0 + p * 32;
            *(ushort4*)&As[0][row][a_c4] = make_ushort4(h[0], h[1], h[2], h[3]);
            *(ushort4*)&As[1][row][a_c4] = make_ushort4(l[0], l[1], l[2], l[3]);
        }
#pragma unroll
        for (int p = 0; p < BP; p++) {
            float v[4] = {pb[p].x, pb[p].y, pb[p].z, pb[p].w};
            unsigned short h[4], l[4];
#pragma unroll
            for (int j = 0; j < 4; j++) split_bf16(v[j], h[j], l[j]);
            int colt = b_c4 + p * 32;
            *(ushort4*)&Bs[0][b_row][colt] = make_ushort4(h[0], h[1], h[2], h[3]);
            *(ushort4*)&Bs[1][b_row][colt] = make_ushort4(l[0], l[1], l[2], l[3]);
        }
        __syncthreads();

        // ---- prefetch chunk c+1 (overlaps MMA below) ----
        const bool more = (c + 1 < nc);
        if (more) { ldgA(k0 + BK); ldgB(k0 + BK); }

        // ---- MMA on chunk c ----
#pragma unroll
        for (int ks = 0; ks < 2; ks++) {
            uint32_t ah[2][4], al[2][4];
#pragma unroll
            for (int tm = 0; tm < 2; tm++) {
                int r = warp_m * 32 + tm * 16 + (lane & 15);
                int cc = ks * 16 + (lane >> 4) * 8;
                ldm_x4(ah[tm], &As[0][r][cc]);
                ldm_x4(al[tm], &As[1][r][cc]);
            }
            uint32_t bh[NG][4], bl[NG][4];
#pragma unroll
            for (int ng = 0; ng < NG; ng++) {
                int r = ks * 16 + (lane & 15);
                int cc = warp_n * BN_W + ng * 16 + (lane >> 4) * 8;
                ldm_x4_t(bh[ng], &Bs[0][r][cc]);
                ldm_x4_t(bl[ng], &Bs[1][r][cc]);
            }
#pragma unroll
            for (int tm = 0; tm < 2; tm++)
#pragma unroll
                for (int nn = 0; nn < NT; nn++) {
                    const uint32_t* bH = &bh[nn >> 1][(nn & 1) * 2];
                    const uint32_t* bL = &bl[nn >> 1][(nn & 1) * 2];
                    mma_bf16(acc[tm][nn], ah[tm], bH);
                    mma_bf16(acc[tm][nn], ah[tm], bL);
                    mma_bf16(acc[tm][nn], al[tm], bH);
                }
        }
        if (more) __syncthreads();
    }

    // ---- epilogue ----
    const int warpCol = colBase + warp_n * BN_W;
    float ls[NT][2], lss[NT][2];
    if (DO_STATS) {
#pragma unroll
        for (int n = 0; n < NT; n++) {
            ls[n][0] = ls[n][1] = 0.0f;
            lss[n][0] = lss[n][1] = 0.0f;
        }
    }
#pragma unroll
    for (int tm = 0; tm < 2; tm++) {
        int r0 = blockRow + warp_m * 32 + tm * 16 + (lane >> 2);
#pragma unroll
        for (int h = 0; h < 2; h++) {
            long row = r0 + h * 8;
            if (row >= M) continue;
#pragma unroll
            for (int nn = 0; nn < NT; nn++) {
                int col = warpCol + nn * 8 + (lane & 3) * 2;
                if (col >= Nr) continue;
                float2 v = make_float2(acc[tm][nn][h * 2], acc[tm][nn][h * 2 + 1]);
                if (bias) {
                    v.x += __ldg(&bias[col]);
                    v.y += __ldg(&bias[col + 1]);
                }
                *(float2*)&xw[row * Nr + col] = v;
                if (DO_STATS) {
                    ls[nn][0] += v.x;  lss[nn][0] += v.x * v.x;
                    ls[nn][1] += v.y;  lss[nn][1] += v.y * v.y;
                }
            }
        }
    }
    if (DO_STATS) {
        // reduce across the 8 lanes sharing (lane&3), then REDG per column
#pragma unroll
        for (int nn = 0; nn < NT; nn++)
#pragma unroll
            for (int j = 0; j < 2; j++) {
#pragma unroll
                for (int mask = 4; mask < 32; mask <<= 1) {
                    ls[nn][j]  += __shfl_xor_sync(0xFFFFFFFFu, ls[nn][j], mask);
                    lss[nn][j] += __shfl_xor_sync(0xFFFFFFFFu, lss[nn][j], mask);
                }
            }
        if (lane < 4) {
#pragma unroll
            for (int nn = 0; nn < NT; nn++) {
                int col = warpCol + nn * 8 + lane * 2;
                atomicAdd(&g_sum[col],       ls[nn][0]);
                atomicAdd(&g_sum[col + 1],   ls[nn][1]);
                atomicAdd(&g_sumsq[col],     lss[nn][0]);
                atomicAdd(&g_sumsq[col + 1], lss[nn][1]);
            }
        }
    }
}

// ---------------- CSR gather aggregation (no atomics) ----------------
__global__ void k_gather128(float* __restrict__ out, const float* __restrict__ x, int n) {
    int node = (blockIdx.x * blockDim.x + threadIdx.x) >> 5;
    int lane = threadIdx.x & 31;
    if (node >= n) return;
    float dv = g_dinv[node];
    float dv2 = dv * dv;
    const float4* xs4 = (const float4*)x;
    float4 s = xs4[(long)node * 32 + lane];
    float4 a = make_float4(dv2 * s.x, dv2 * s.y, dv2 * s.z, dv2 * s.w);
    int b = g_rowstart[node], e = b + g_cnt[node];
    for (int p = b; p < e; p++) {
        int src = g_esrc[p];
        float nm = g_enrm[p];
        float4 v = __ldg(&xs4[(long)src * 32 + lane]);
        a.x = fmaf(nm, v.x, a.x); a.y = fmaf(nm, v.y, a.y);
        a.z = fmaf(nm, v.z, a.z); a.w = fmaf(nm, v.w, a.w);
    }
    ((float4*)out)[(long)node * 32 + lane] = a;
}

__global__ void k_gather256(float* __restrict__ out, const float* __restrict__ xw,
                            const float* __restrict__ bias, int n) {
    int node = (blockIdx.x * blockDim.x + threadIdx.x) >> 5;
    int lane = threadIdx.x & 31;
    if (node >= n) return;
    float dv = g_dinv[node];
    float dv2 = dv * dv;
    const float4* xself = (const float4*)(xw + (long)node * HIDDEN);
    float4 s0 = xself[lane];
    float4 s1 = xself[lane + 32];
    float4 a0 = make_float4(dv2 * s0.x, dv2 * s0.y, dv2 * s0.z, dv2 * s0.w);
    float4 a1 = make_float4(dv2 * s1.x, dv2 * s1.y, dv2 * s1.z, dv2 * s1.w);
    int b = g_rowstart[node], e = b + g_cnt[node];
    for (int p = b; p < e; p++) {
        int src = g_esrc[p];
        float nm = g_enrm[p];
        const float4* xs = (const float4*)(xw + (long)src * HIDDEN);
        float4 v0 = __ldg(&xs[lane]);
        float4 v1 = __ldg(&xs[lane + 32]);
        a0.x = fmaf(nm, v0.x, a0.x); a0.y = fmaf(nm, v0.y, a0.y);
        a0.z = fmaf(nm, v0.z, a0.z); a0.w = fmaf(nm, v0.w, a0.w);
        a1.x = fmaf(nm, v1.x, a1.x); a1.y = fmaf(nm, v1.y, a1.y);
        a1.z = fmaf(nm, v1.z, a1.z); a1.w = fmaf(nm, v1.w, a1.w);
    }
    const float4* b4 = (const float4*)bias;
    float4 bb0 = __ldg(&b4[lane]);
    float4 bb1 = __ldg(&b4[lane + 32]);
    a0.x += bb0.x; a0.y += bb0.y; a0.z += bb0.z; a0.w += bb0.w;
    a1.x += bb1.x; a1.y += bb1.y; a1.z += bb1.z; a1.w += bb1.w;
    float4* o = (float4*)(out + (long)node * HIDDEN);
    o[lane] = a0;
    o[lane + 32] = a1;
}

// width 40 gather + bias + log_softmax fused (warp per node)
__global__ void k_gather40_lsm(float* __restrict__ out, const float* __restrict__ xw,
                               const float* __restrict__ bias, int n) {
    int node = (blockIdx.x * blockDim.x + threadIdx.x) >> 5;
    int lane = threadIdx.x & 31;
    if (node >= n) return;
    float dv = g_dinv[node];
    float dv2 = dv * dv;
    const float* xself = xw + (long)node * N_CLASSES;
    bool hi = (lane + 32 < N_CLASSES);
    float a0 = dv2 * xself[lane];
    float a1 = hi ? dv2 * xself[lane + 32] : 0.0f;
    int b = g_rowstart[node], e = b + g_cnt[node];
    for (int p = b; p < e; p++) {
        int src = g_esrc[p];
        float nm = g_enrm[p];
        const float* xs = xw + (long)src * N_CLASSES;
        a0 = fmaf(nm, __ldg(&xs[lane]), a0);
        if (hi) a1 = fmaf(nm, __ldg(&xs[lane + 32]), a1);
    }
    a0 += __ldg(&bias[lane]);
    if (hi) a1 += __ldg(&bias[lane + 32]);
    // log-softmax over 40 values
    float m = fmaxf(a0, hi ? a1 : -1e30f);
#pragma unroll
    for (int o = 16; o > 0; o >>= 1)
        m = fmaxf(m, __shfl_xor_sync(0xFFFFFFFFu, m, o));
    float s = expf(a0 - m) + (hi ? expf(a1 - m) : 0.0f);
#pragma unroll
    for (int o = 16; o > 0; o >>= 1)
        s += __shfl_xor_sync(0xFFFFFFFFu, s, o);
    float lse = m + logf(s);
    float* orow = out + (long)node * N_CLASSES;
    orow[lane] = a0 - lse;
    if (hi) orow[lane + 32] = a1 - lse;
}

// ---------------- batchnorm ----------------
__global__ void k_bn_stats(const float* __restrict__ h, int n) {
    int c = threadIdx.x;
    int chunk = (n + gridDim.x - 1) / gridDim.x;
    int r0 = blockIdx.x * chunk;
    int r1 = min(n, r0 + chunk);
    float s = 0.0f, ss = 0.0f;
    for (int r = r0; r < r1; r++) {
        float v = h[(long)r * HIDDEN + c];
        s += v;
        ss += v * v;
    }
    atomicAdd(&g_sum[c], s);
    atomicAdd(&g_sumsq[c], ss);
}
// finalize + re-zero stats for next layer
__global__ void k_bn_finalize(const float* __restrict__ gamma,
                              const float* __restrict__ beta, int n) {
    int c = threadIdx.x;
    float inv_n = 1.0f / (float)n;
    float mean = g_sum[c] * inv_n;
    float var  = g_sumsq[c] * inv_n - mean * mean;
    float sc = gamma[c] * rsqrtf(var + BN_EPS);
    g_scale[c] = sc;
    g_shift[c] = beta[c] - mean * sc;
    g_sum[c] = 0.0f;
    g_sumsq[c] = 0.0f;
}

// ---------------- launch ----------------
extern "C" void kernel_launch(void* const* d_in, const int* in_sizes, int n_in,
                              void* d_out, int out_size) {
    const float* x   = (const float*)d_in[0];
    const void*  ei  = d_in[1];
    const float* W1  = (const float*)d_in[2];
    const float* b1  = (const float*)d_in[3];
    const float* g1  = (const float*)d_in[4];
    const float* be1 = (const float*)d_in[5];
    const float* W2  = (const float*)d_in[6];
    const float* b2  = (const float*)d_in[7];
    const float* g2  = (const float*)d_in[8];
    const float* be2 = (const float*)d_in[9];
    const float* W3  = (const float*)d_in[10];
    const float* b3  = (const float*)d_in[11];
    float* out = (float*)d_out;

    const int N = N_NODES;
    const int E = in_sizes[1] / 2;

    float *pA, *pB, *pC, *pScale, *pShift;
    cudaGetSymbolAddress((void**)&pA, g_bufA);
    cudaGetSymbolAddress((void**)&pB, g_bufB);
    cudaGetSymbolAddress((void**)&pC, g_bufC);
    cudaGetSymbolAddress((void**)&pScale, g_scale);
    cudaGetSymbolAddress((void**)&pShift, g_shift);

    // ---- CSR preamble (4 launches) ----
    k_detect_zero<<<(N + 255) / 256, 256>>>((const int*)ei, N);
    k_hist<<<(E + 255) / 256, 256>>>(ei, E);
    k_reserve<<<(N + 255) / 256, 256>>>(N);
    k_fill<<<(E + 255) / 256, 256>>>(ei, E);

    const int mTiles = (N + 127) / 128;
    dim3 gHid(mTiles, 2);
    dim3 gCls(mTiles, 1);
    int gatherBlocks = (N * 32 + 255) / 256;

    // ---- layer 1: h1 = (ÂX)W1 + b1 ; BN stats fused into gemm epilogue ----
    k_gather128<<<gatherBlocks, 256>>>(pB, x, N);
    gemm_mma<128, true><<<gHid, 256>>>(pB, W1, nullptr, nullptr, b1, pA, N, IN_FEAT, HIDDEN);
    k_bn_finalize<<<1, HIDDEN>>>(g1, be1, N);

    // ---- layer 2 ----
    gemm_mma<128, false><<<gHid, 256>>>(pA, W2, pScale, pShift, nullptr, pB, N, HIDDEN, HIDDEN);
    k_gather256<<<gatherBlocks, 256>>>(pC, pB, b2, N);
    k_bn_stats<<<512, HIDDEN>>>(pC, N);
    k_bn_finalize<<<1, HIDDEN>>>(g2, be2, N);

    // ---- layer 3 (gather + log_softmax fused) ----
    gemm_mma<64, false><<<gCls, 256>>>(pC, W3, pScale, pShift, nullptr, pA, N, HIDDEN, N_CLASSES);
    k_gather40_lsm<<<gatherBlocks, 256>>>(out, pA, b3, N);
}

// round 8
// speedup vs baseline: 1.0748x; 1.0748x over previous
#include <cuda_runtime.h>
#include <cuda_bf16.h>
#include <math.h>
#include <stdint.h>

#define N_NODES   50000
#define IN_FEAT   128
#define HIDDEN    256
#define N_CLASSES 40
#define MAX_E     320000
#define BN_EPS    1e-5f

// ---------------- scratch (device globals; zero-initialized at load) ----------------
__device__ float g_bufA[N_NODES * HIDDEN];
__device__ float g_bufB[N_NODES * HIDDEN];
__device__ float g_bufC[N_NODES * HIDDEN];
__device__ float g_dinv[N_NODES];
__device__ int   g_cnt[N_NODES];       // zero at load; self-cleaned each run
__device__ int   g_rowstart[N_NODES];
__device__ int   g_cursor[N_NODES];
__device__ int   g_total;              // zero at load; self-cleaned each run
__device__ int   g_esrc[MAX_E];
__device__ float g_enrm[MAX_E];
__device__ float g_sum[HIDDEN];        // zero at load; re-zeroed by bn_finalize
__device__ float g_sumsq[HIDDEN];
__device__ float g_scale[HIDDEN];
__device__ float g_shift[HIDDEN];

// ---------------- per-block edge dtype probe ----------------
// int64 edge_index (values < 50000, little-endian) => odd 32-bit words all 0.
__device__ __forceinline__ int probe_is64(const int* ei32) {
    int probe = ei32[2 * (threadIdx.x & 127) + 1];
    return (__syncthreads_or(probe) == 0) ? 1 : 0;
}
__device__ __forceinline__ int eget(const void* ei, long pos, int is64) {
    if (is64) return (int)__ldg(((const long long*)ei) + pos);
    return __ldg(((const int*)ei) + pos);
}

// ---------------- CSR build (unordered segments) ----------------
__global__ void k_hist(const void* __restrict__ ei, int E) {
    int is64 = probe_is64((const int*)ei);
    int e = blockIdx.x * blockDim.x + threadIdx.x;
    if (e >= E) return;
    atomicAdd(&g_cnt[eget(ei, (long)E + e, is64)], 1);
}
__global__ void k_reserve(int n) {
    int i = blockIdx.x * blockDim.x + threadIdx.x;
    if (i >= n) return;
    int c = g_cnt[i];
    g_dinv[i] = rsqrtf(1.0f + (float)c);
    int pos = atomicAdd(&g_total, c);
    g_rowstart[i] = pos;
    g_cursor[i] = pos;
}
__global__ void k_fill(const void* __restrict__ ei, int E) {
    int is64 = probe_is64((const int*)ei);
    int e = blockIdx.x * blockDim.x + threadIdx.x;
    if (e >= E) return;
    int s = eget(ei, e, is64);
    int d = eget(ei, (long)E + e, is64);
    int pos = atomicAdd(&g_cursor[d], 1);
    g_esrc[pos] = s;
    g_enrm[pos] = g_dinv[s] * g_dinv[d];
}

// ---------------- HMMA helpers ----------------
__device__ __forceinline__ void ldm_x4(uint32_t* r, const void* p) {
    uint32_t a = (uint32_t)__cvta_generic_to_shared(p);
    asm volatile("ldmatrix.sync.aligned.m8n8.x4.shared.b16 {%0,%1,%2,%3}, [%4];"
                 : "=r"(r[0]), "=r"(r[1]), "=r"(r[2]), "=r"(r[3]) : "r"(a));
}
__device__ __forceinline__ void ldm_x4_t(uint32_t* r, const void* p) {
    uint32_t a = (uint32_t)__cvta_generic_to_shared(p);
    asm volatile("ldmatrix.sync.aligned.m8n8.x4.trans.shared.b16 {%0,%1,%2,%3}, [%4];"
                 : "=r"(r[0]), "=r"(r[1]), "=r"(r[2]), "=r"(r[3]) : "r"(a));
}
__device__ __forceinline__ void mma_bf16(float* c, const uint32_t* a, const uint32_t* b) {
    asm volatile(
        "mma.sync.aligned.m16n8k16.row.col.f32.bf16.bf16.f32 "
        "{%0,%1,%2,%3}, {%4,%5,%6,%7}, {%8,%9}, {%0,%1,%2,%3};"
        : "+f"(c[0]), "+f"(c[1]), "+f"(c[2]), "+f"(c[3])
        : "r"(a[0]), "r"(a[1]), "r"(a[2]), "r"(a[3]), "r"(b[0]), "r"(b[1]));
}
// truncation hi/lo split of a float pair: hi2 = packed top-16-bits, lo2 = bf16x2 of residual
__device__ __forceinline__ void split2(float v0, float v1, uint32_t& hi2, uint32_t& lo2) {
    uint32_t b0 = __float_as_uint(v0), b1 = __float_as_uint(v1);
    hi2 = __byte_perm(b0, b1, 0x7632);
    float l0 = v0 - __uint_as_float(b0 & 0xFFFF0000u);
    float l1 = v1 - __uint_as_float(b1 & 0xFFFF0000u);
    asm("cvt.rn.satfinite.bf16x2.f32 %0, %1, %2;" : "=r"(lo2) : "f"(l1), "f"(l0));
}

// ---------------- HMMA GEMM, 2-stage smem double buffer ----------------
// xw = act(A) @ W (+ bias); act = relu(a*scale+shift) if scale; 3-product bf16 hi/lo.
template <int BN_T, bool DO_STATS>
__global__ void __launch_bounds__(256) gemm_mma(
    const float* __restrict__ A, const float* __restrict__ W,
    const float* __restrict__ scale, const float* __restrict__ shift,
    const float* __restrict__ bias,
    float* __restrict__ xw,
    int M, int K, int Nr)
{
    constexpr int BM = 128, BK = 32;
    constexpr int ASTR = BK + 8;            // 40
    constexpr int BSTR = BN_T + 8;
    constexpr int BN_W = BN_T / 2;
    constexpr int NT = BN_W / 8;
    constexpr int NG = BN_W / 16;
    constexpr int BP = BN_T / 32;
    constexpr int ABYTES = BM * ASTR * 2;   // 10240
    constexpr int BBYTES = BK * BSTR * 2;
    constexpr int STAGE  = 2 * ABYTES + 2 * BBYTES;

    extern __shared__ char dsm[];
    __shared__ float sSc[HIDDEN], sSh[HIDDEN];

    const int tid = threadIdx.x;
    const int wid = tid >> 5, lane = tid & 31;
    const int warp_m = wid >> 1, warp_n = wid & 1;
    const int blockRow = blockIdx.x * BM;
    const int colBase = blockIdx.y * BN_T;
    const bool useScale = (scale != nullptr);

    auto AHp = [&](int s) { return (__nv_bfloat16*)(dsm + s * STAGE); };
    auto ALp = [&](int s) { return (__nv_bfloat16*)(dsm + s * STAGE + ABYTES); };
    auto BHp = [&](int s) { return (__nv_bfloat16*)(dsm + s * STAGE + 2 * ABYTES); };
    auto BLp = [&](int s) { return (__nv_bfloat16*)(dsm + s * STAGE + 2 * ABYTES + BBYTES); };

    const int a_row0 = tid >> 3;            // 0..31
    const int a_c4   = (tid & 7) * 4;       // 0..28
    const int b_row  = tid >> 3;
    const int b_c4   = (tid & 7) * 4;

    float4 pa[4], pb[BP];

    auto ldgA = [&](int k0) {
#pragma unroll
        for (int p = 0; p < 4; p++) {
            long gr = blockRow + a_row0 + p * 32;
            if (gr < M) pa[p] = *(const float4*)&A[gr * K + k0 + a_c4];
            else pa[p] = make_float4(0.f, 0.f, 0.f, 0.f);
        }
    };
    auto ldgB = [&](int k0) {
#pragma unroll
        for (int p = 0; p < BP; p++) {
            int gcol = colBase + b_c4 + p * 32;
            if (gcol < Nr) pb[p] = *(const float4*)&W[(long)(k0 + b_row) * Nr + gcol];
            else pb[p] = make_float4(0.f, 0.f, 0.f, 0.f);
        }
    };
    auto cvtA = [&](int s, int k0) {
        __nv_bfloat16* AH = AHp(s);
        __nv_bfloat16* AL = ALp(s);
#pragma unroll
        for (int p = 0; p < 4; p++) {
            float v[4] = {pa[p].x, pa[p].y, pa[p].z, pa[p].w};
            if (useScale) {
#pragma unroll
                for (int j = 0; j < 4; j++)
                    v[j] = fmaxf(0.0f, fmaf(v[j], sSc[k0 + a_c4 + j], sSh[k0 + a_c4 + j]));
            }
            uint32_t h0, l0, h1, l1;
            split2(v[0], v[1], h0, l0);
            split2(v[2], v[3], h1, l1);
            int row = a_row0 + p * 32;
            *(uint2*)&AH[row * ASTR + a_c4] = make_uint2(h0, h1);
            *(uint2*)&AL[row * ASTR + a_c4] = make_uint2(l0, l1);
        }
    };
    auto cvtB = [&](int s) {
        __nv_bfloat16* BH = BHp(s);
        __nv_bfloat16* BL = BLp(s);
#pragma unroll
        for (int p = 0; p < BP; p++) {
            uint32_t h0, l0, h1, l1;
            split2(pb[p].x, pb[p].y, h0, l0);
            split2(pb[p].z, pb[p].w, h1, l1);
            int colt = b_c4 + p * 32;
            *(uint2*)&BH[b_row * BSTR + colt] = make_uint2(h0, h1);
            *(uint2*)&BL[b_row * BSTR + colt] = make_uint2(l0, l1);
        }
    };

    float acc[2][NT][4];
#pragma unroll
    for (int m = 0; m < 2; m++)
#pragma unroll
        for (int n = 0; n < NT; n++)
#pragma unroll
            for (int j = 0; j < 4; j++) acc[m][n][j] = 0.0f;

    auto doMMA = [&](int s) {
        __nv_bfloat16* AH = AHp(s);
        __nv_bfloat16* AL = ALp(s);
        __nv_bfloat16* BH = BHp(s);
        __nv_bfloat16* BL = BLp(s);
#pragma unroll
        for (int ks = 0; ks < 2; ks++) {
            uint32_t ah[2][4], al[2][4];
#pragma unroll
            for (int tm = 0; tm < 2; tm++) {
                int r = warp_m * 32 + tm * 16 + (lane & 15);
                int cc = ks * 16 + (lane >> 4) * 8;
                ldm_x4(ah[tm], &AH[r * ASTR + cc]);
                ldm_x4(al[tm], &AL[r * ASTR + cc]);
            }
            uint32_t bh[NG][4], bl[NG][4];
#pragma unroll
            for (int ng = 0; ng < NG; ng++) {
                int r = ks * 16 + (lane & 15);
                int cc = warp_n * BN_W + ng * 16 + (lane >> 4) * 8;
                ldm_x4_t(bh[ng], &BH[r * BSTR + cc]);
                ldm_x4_t(bl[ng], &BL[r * BSTR + cc]);
            }
#pragma unroll
            for (int tm = 0; tm < 2; tm++)
#pragma unroll
                for (int nn = 0; nn < NT; nn++) {
                    const uint32_t* bH = &bh[nn >> 1][(nn & 1) * 2];
                    const uint32_t* bL = &bl[nn >> 1][(nn & 1) * 2];
                    mma_bf16(acc[tm][nn], ah[tm], bH);
                    mma_bf16(acc[tm][nn], ah[tm], bL);
                    mma_bf16(acc[tm][nn], al[tm], bH);
                }
        }
    };

    // ---- prologue ----
    ldgA(0); ldgB(0);
    if (useScale) {
        for (int i = tid; i < K; i += 256) { sSc[i] = scale[i]; sSh[i] = shift[i]; }
        __syncthreads();
    }
    cvtA(0, 0); cvtB(0);
    __syncthreads();

    const int nc = K / BK;
    for (int c = 0; c < nc; c++) {
        const bool more = (c + 1 < nc);
        if (more) { ldgA((c + 1) * BK); ldgB((c + 1) * BK); }
        doMMA(c & 1);
        if (more) {
            cvtA((c + 1) & 1, (c + 1) * BK);
            cvtB((c + 1) & 1);
            __syncthreads();
        }
    }

    // ---- epilogue ----
    const int warpCol = colBase + warp_n * BN_W;
    float ls[NT][2], lss[NT][2];
    if (DO_STATS) {
#pragma unroll
        for (int n = 0; n < NT; n++) {
            ls[n][0] = ls[n][1] = 0.0f;
            lss[n][0] = lss[n][1] = 0.0f;
        }
    }
#pragma unroll
    for (int tm = 0; tm < 2; tm++) {
        int r0 = blockRow + warp_m * 32 + tm * 16 + (lane >> 2);
#pragma unroll
        for (int h = 0; h < 2; h++) {
            long row = r0 + h * 8;
            if (row >= M) continue;
#pragma unroll
            for (int nn = 0; nn < NT; nn++) {
                int col = warpCol + nn * 8 + (lane & 3) * 2;
                if (col >= Nr) continue;
                float2 v = make_float2(acc[tm][nn][h * 2], acc[tm][nn][h * 2 + 1]);
                if (bias) {
                    v.x += __ldg(&bias[col]);
                    v.y += __ldg(&bias[col + 1]);
                }
                *(float2*)&xw[row * Nr + col] = v;
                if (DO_STATS) {
                    ls[nn][0] += v.x;  lss[nn][0] += v.x * v.x;
                    ls[nn][1] += v.y;  lss[nn][1] += v.y * v.y;
                }
            }
        }
    }
    if (DO_STATS) {
#pragma unroll
        for (int nn = 0; nn < NT; nn++)
#pragma unroll
            for (int j = 0; j < 2; j++) {
#pragma unroll
                for (int mask = 4; mask < 32; mask <<= 1) {
                    ls[nn][j]  += __shfl_xor_sync(0xFFFFFFFFu, ls[nn][j], mask);
                    lss[nn][j] += __shfl_xor_sync(0xFFFFFFFFu, lss[nn][j], mask);
                }
            }
        if (lane < 4) {
#pragma unroll
            for (int nn = 0; nn < NT; nn++) {
                int col = warpCol + nn * 8 + lane * 2;
                atomicAdd(&g_sum[col],       ls[nn][0]);
                atomicAdd(&g_sum[col + 1],   ls[nn][1]);
                atomicAdd(&g_sumsq[col],     lss[nn][0]);
                atomicAdd(&g_sumsq[col + 1], lss[nn][1]);
            }
        }
    }
}

// ---------------- CSR gather aggregation (2-edge unrolled, no atomics) ----------------
__global__ void k_gather128(float* __restrict__ out, const float* __restrict__ x, int n) {
    int node = (blockIdx.x * blockDim.x + threadIdx.x) >> 5;
    int lane = threadIdx.x & 31;
    if (node >= n) return;
    float dv = g_dinv[node];
    float dv2 = dv * dv;
    const float4* xs4 = (const float4*)x;
    float4 s = xs4[(long)node * 32 + lane];
    float4 a = make_float4(dv2 * s.x, dv2 * s.y, dv2 * s.z, dv2 * s.w);
    int b = g_rowstart[node], e = b + g_cnt[node];
    int p = b;
    for (; p + 1 < e; p += 2) {
        int s0 = g_esrc[p], s1 = g_esrc[p + 1];
        float n0 = g_enrm[p], n1 = g_enrm[p + 1];
        float4 v0 = __ldg(&xs4[(long)s0 * 32 + lane]);
        float4 v1 = __ldg(&xs4[(long)s1 * 32 + lane]);
        a.x = fmaf(n0, v0.x, fmaf(n1, v1.x, a.x));
        a.y = fmaf(n0, v0.y, fmaf(n1, v1.y, a.y));
        a.z = fmaf(n0, v0.z, fmaf(n1, v1.z, a.z));
        a.w = fmaf(n0, v0.w, fmaf(n1, v1.w, a.w));
    }
    if (p < e) {
        float nm = g_enrm[p];
        float4 v = __ldg(&xs4[(long)g_esrc[p] * 32 + lane]);
        a.x = fmaf(nm, v.x, a.x); a.y = fmaf(nm, v.y, a.y);
        a.z = fmaf(nm, v.z, a.z); a.w = fmaf(nm, v.w, a.w);
    }
    ((float4*)out)[(long)node * 32 + lane] = a;
}

__global__ void k_gather256(float* __restrict__ out, const float* __restrict__ xw,
                            const float* __restrict__ bias, int n) {
    int node = (blockIdx.x * blockDim.x + threadIdx.x) >> 5;
    int lane = threadIdx.x & 31;
    if (node >= n) return;
    float dv = g_dinv[node];
    float dv2 = dv * dv;
    const float4* xself = (const float4*)(xw + (long)node * HIDDEN);
    float4 s0 = xself[lane];
    float4 s1 = xself[lane + 32];
    float4 a0 = make_float4(dv2 * s0.x, dv2 * s0.y, dv2 * s0.z, dv2 * s0.w);
    float4 a1 = make_float4(dv2 * s1.x, dv2 * s1.y, dv2 * s1.z, dv2 * s1.w);
    int b = g_rowstart[node], e = b + g_cnt[node];
    int p = b;
    for (; p + 1 < e; p += 2) {
        int sA = g_esrc[p], sB = g_esrc[p + 1];
        float nA = g_enrm[p], nB = g_enrm[p + 1];
        const float4* xa = (const float4*)(xw + (long)sA * HIDDEN);
        const float4* xb = (const float4*)(xw + (long)sB * HIDDEN);
        float4 va0 = __ldg(&xa[lane]);
        float4 va1 = __ldg(&xa[lane + 32]);
        float4 vb0 = __ldg(&xb[lane]);
        float4 vb1 = __ldg(&xb[lane + 32]);
        a0.x = fmaf(nA, va0.x, fmaf(nB, vb0.x, a0.x));
        a0.y = fmaf(nA, va0.y, fmaf(nB, vb0.y, a0.y));
        a0.z = fmaf(nA, va0.z, fmaf(nB, vb0.z, a0.z));
        a0.w = fmaf(nA, va0.w, fmaf(nB, vb0.w, a0.w));
        a1.x = fmaf(nA, va1.x, fmaf(nB, vb1.x, a1.x));
        a1.y = fmaf(nA, va1.y, fmaf(nB, vb1.y, a1.y));
        a1.z = fmaf(nA, va1.z, fmaf(nB, vb1.z, a1.z));
        a1.w = fmaf(nA, va1.w, fmaf(nB, vb1.w, a1.w));
    }
    if (p < e) {
        int sA = g_esrc[p];
        float nA = g_enrm[p];
        const float4* xa = (const float4*)(xw + (long)sA * HIDDEN);
        float4 va0 = __ldg(&xa[lane]);
        float4 va1 = __ldg(&xa[lane + 32]);
        a0.x = fmaf(nA, va0.x, a0.x); a0.y = fmaf(nA, va0.y, a0.y);
        a0.z = fmaf(nA, va0.z, a0.z); a0.w = fmaf(nA, va0.w, a0.w);
        a1.x = fmaf(nA, va1.x, a1.x); a1.y = fmaf(nA, va1.y, a1.y);
        a1.z = fmaf(nA, va1.z, a1.z); a1.w = fmaf(nA, va1.w, a1.w);
    }
    const float4* b4 = (const float4*)bias;
    float4 bb0 = __ldg(&b4[lane]);
    float4 bb1 = __ldg(&b4[lane + 32]);
    a0.x += bb0.x; a0.y += bb0.y; a0.z += bb0.z; a0.w += bb0.w;
    a1.x += bb1.x; a1.y += bb1.y; a1.z += bb1.z; a1.w += bb1.w;
    float4* o = (float4*)(out + (long)node * HIDDEN);
    o[lane] = a0;
    o[lane + 32] = a1;
}

// width-40 gather + bias + log_softmax fused; self-cleans g_cnt / g_total
__global__ void k_gather40_lsm(float* __restrict__ out, const float* __restrict__ xw,
                               const float* __restrict__ bias, int n) {
    int node = (blockIdx.x * blockDim.x + threadIdx.x) >> 5;
    int lane = threadIdx.x & 31;
    if (node >= n) return;
    float dv = g_dinv[node];
    float dv2 = dv * dv;
    const float* xself = xw + (long)node * N_CLASSES;
    bool hi = (lane + 32 < N_CLASSES);
    float a0 = dv2 * xself[lane];
    float a1 = hi ? dv2 * xself[lane + 32] : 0.0f;
    int b = g_rowstart[node], e = b + g_cnt[node];
    int p = b;
    for (; p + 1 < e; p += 2) {
        int sA = g_esrc[p], sB = g_esrc[p + 1];
        float nA = g_enrm[p], nB = g_enrm[p + 1];
        const float* xa = xw + (long)sA * N_CLASSES;
        const float* xb = xw + (long)sB * N_CLASSES;
        float va0 = __ldg(&xa[lane]);
        float vb0 = __ldg(&xb[lane]);
        a0 = fmaf(nA, va0, fmaf(nB, vb0, a0));
        if (hi) {
            float va1 = __ldg(&xa[lane + 32]);
            float vb1 = __ldg(&xb[lane + 32]);
            a1 = fmaf(nA, va1, fmaf(nB, vb1, a1));
        }
    }
    if (p < e) {
        int sA = g_esrc[p];
        float nA = g_enrm[p];
        const float* xa = xw + (long)sA * N_CLASSES;
        a0 = fmaf(nA, __ldg(&xa[lane]), a0);
        if (hi) a1 = fmaf(nA, __ldg(&xa[lane + 32]), a1);
    }
    a0 += __ldg(&bias[lane]);
    if (hi) a1 += __ldg(&bias[lane + 32]);
    // log-softmax over 40 values
    float m = fmaxf(a0, hi ? a1 : -1e30f);
#pragma unroll
    for (int o = 16; o > 0; o >>= 1)
        m = fmaxf(m, __shfl_xor_sync(0xFFFFFFFFu, m, o));
    float s = expf(a0 - m) + (hi ? expf(a1 - m) : 0.0f);
#pragma unroll
    for (int o = 16; o > 0; o >>= 1)
        s += __shfl_xor_sync(0xFFFFFFFFu, s, o);
    float lse = m + logf(s);
    float* orow = out + (long)node * N_CLASSES;
    orow[lane] = a0 - lse;
    if (hi) orow[lane + 32] = a1 - lse;
    // self-clean for the next graph replay
    if (lane == 0) g_cnt[node] = 0;
    if (node == 0 && lane == 0) g_total = 0;
}

// ---------------- batchnorm ----------------
__global__ void k_bn_stats(const float* __restrict__ h, int n) {
    int c = threadIdx.x;
    int chunk = (n + gridDim.x - 1) / gridDim.x;
    int r0 = blockIdx.x * chunk;
    int r1 = min(n, r0 + chunk);
    float s = 0.0f, ss = 0.0f;
    for (int r = r0; r < r1; r++) {
        float v = h[(long)r * HIDDEN + c];
        s += v;
        ss += v * v;
    }
    atomicAdd(&g_sum[c], s);
    atomicAdd(&g_sumsq[c], ss);
}
__global__ void k_bn_finalize(const float* __restrict__ gamma,
                              const float* __restrict__ beta, int n) {
    int c = threadIdx.x;
    float inv_n = 1.0f / (float)n;
    float mean = g_sum[c] * inv_n;
    float var  = g_sumsq[c] * inv_n - mean * mean;
    float sc = gamma[c] * rsqrtf(var + BN_EPS);
    g_scale[c] = sc;
    g_shift[c] = beta[c] - mean * sc;
    g_sum[c] = 0.0f;
    g_sumsq[c] = 0.0f;
}

// ---------------- launch ----------------
#define SMEM_GEMM_128  (2 * (2 * 128 * 40 * 2 + 2 * 32 * 136 * 2))   // 75776
#define SMEM_GEMM_64   (2 * (2 * 128 * 40 * 2 + 2 * 32 * 72 * 2))    // 59392

extern "C" void kernel_launch(void* const* d_in, const int* in_sizes, int n_in,
                              void* d_out, int out_size) {
    const float* x   = (const float*)d_in[0];
    const void*  ei  = d_in[1];
    const float* W1  = (const float*)d_in[2];
    const float* b1  = (const float*)d_in[3];
    const float* g1  = (const float*)d_in[4];
    const float* be1 = (const float*)d_in[5];
    const float* W2  = (const float*)d_in[6];
    const float* b2  = (const float*)d_in[7];
    const float* g2  = (const float*)d_in[8];
    const float* be2 = (const float*)d_in[9];
    const float* W3  = (const float*)d_in[10];
    const float* b3  = (const float*)d_in[11];
    float* out = (float*)d_out;

    const int N = N_NODES;
    const int E = in_sizes[1] / 2;

    float *pA, *pB, *pC, *pScale, *pShift;
    cudaGetSymbolAddress((void**)&pA, g_bufA);
    cudaGetSymbolAddress((void**)&pB, g_bufB);
    cudaGetSymbolAddress((void**)&pC, g_bufC);
    cudaGetSymbolAddress((void**)&pScale, g_scale);
    cudaGetSymbolAddress((void**)&pShift, g_shift);

    cudaFuncSetAttribute(gemm_mma<128, true>,
                         cudaFuncAttributeMaxDynamicSharedMemorySize, SMEM_GEMM_128);
    cudaFuncSetAttribute(gemm_mma<128, false>,
                         cudaFuncAttributeMaxDynamicSharedMemorySize, SMEM_GEMM_128);
    cudaFuncSetAttribute(gemm_mma<64, false>,
                         cudaFuncAttributeMaxDynamicSharedMemorySize, SMEM_GEMM_64);

    // ---- CSR preamble (3 launches; g_cnt/g_total arrive zeroed) ----
    k_hist<<<(E + 255) / 256, 256>>>(ei, E);
    k_reserve<<<(N + 255) / 256, 256>>>(N);
    k_fill<<<(E + 255) / 256, 256>>>(ei, E);

    const int mTiles = (N + 127) / 128;
    dim3 gHid(mTiles, 2);
    dim3 gCls(mTiles, 1);
    int gatherBlocks = (N * 32 + 255) / 256;

    // ---- layer 1: h1 = (ÂX)W1 + b1 ; BN stats fused into gemm epilogue ----
    k_gather128<<<gatherBlocks, 256>>>(pB, x, N);     // launch #4 -> ncu target
    gemm_mma<128, true><<<gHid, 256, SMEM_GEMM_128>>>(pB, W1, nullptr, nullptr, b1,
                                                      pA, N, IN_FEAT, HIDDEN);
    k_bn_finalize<<<1, HIDDEN>>>(g1, be1, N);

    // ---- layer 2 ----
    gemm_mma<128, false><<<gHid, 256, SMEM_GEMM_128>>>(pA, W2, pScale, pShift, nullptr,
                                                       pB, N, HIDDEN, HIDDEN);
    k_gather256<<<gatherBlocks, 256>>>(pC, pB, b2, N);
    k_bn_stats<<<512, HIDDEN>>>(pC, N);
    k_bn_finalize<<<1, HIDDEN>>>(g2, be2, N);

    // ---- layer 3 (gather + log_softmax fused; self-cleaning) ----
    gemm_mma<64, false><<<gCls, 256, SMEM_GEMM_64>>>(pC, W3, pScale, pShift, nullptr,
                                                     pA, N, HIDDEN, N_CLASSES);
    k_gather40_lsm<<<gatherBlocks, 256>>>(out, pA, b3, N);
}